// round 5
// baseline (speedup 1.0000x reference)
#include <cuda_runtime.h>
#include <cstdint>

// Problem constants
#define NSAMPLES   524288
#define NFEAT      64
#define NGATES     64
#define NOUT       8
#define BASEN      66            // NFEAT + 2 (const-0 and const-1 entries)
#define MAXCONN    130           // BASEN + NGATES
#define BLKT       64            // threads per block
#define SPB        128           // samples per block (2 per thread)
#define EST        128           // entry stride in floats (power of 2; banks fixed by swizzle)
#define SMEM_BYTES (MAXCONN * EST * 4)   // 66560 B -> 3 blocks/SM

// XOR swizzle: entry e's row is column-permuted by  col = s ^ (4*((e>>2)&15)).
// Keeps sample-quads (s%4==0) contiguous (bits 0-1 untouched) for STS.128 in
// the transpose and sample-pairs aligned for LDS.64/STS.64 in the gate loop,
// while decorrelating banks from the power-of-2 entry stride.
//   gate LDS.64 / STS.64 : per 16-lane phase, banks = (2t ^ 4j) -> 16 distinct evens. CF.
//   transpose STS.128    : per phase, 4-word spans at (sl ^ 4c) tile all 32 banks. CF.

struct Params {
    uint4 off[NGATES];               // {byteOffA, swzA, byteOffB, swzB}, pre-swizzled
    float w[NGATES][NOUT];           // output_weights * output_scale (pre-folded)
};
__device__   Params g_stage;
__constant__ Params c_p;

// ---------------------------------------------------------------------------
// Prep: top-2 of gate_weights[i, 0 : 66+i]. Softmax is monotonic, so top-2 of
// probs == top-2 of raw logits; lexicographic compare reproduces top_k
// lower-index-wins tie-breaking. Packs swizzled byte offsets; folds scale.
// ---------------------------------------------------------------------------
__global__ void __launch_bounds__(1024)
prep_kernel(const float* __restrict__ gw,
            const float* __restrict__ ow,
            const float* __restrict__ sc) {
    const int tid  = threadIdx.x;
    const int gate = tid >> 4;        // 64 gates
    const int lane = tid & 15;        // 16 threads per gate
    const float* row = gw + gate * MAXCONN;
    const int n = BASEN + gate;

    float v1 = -3.4e38f, v2 = -3.4e38f;
    int   i1 = 0x7fffffff, i2 = 0x7fffffff;
#pragma unroll
    for (int k = 0; k < (MAXCONN + 15) / 16; ++k) {
        int j = lane + k * 16;
        if (j < n) {
            float v = row[j];
            if (v > v1 || (v == v1 && j < i1)) { v2 = v1; i2 = i1; v1 = v; i1 = j; }
            else if (v > v2 || (v == v2 && j < i2)) { v2 = v; i2 = j; }
        }
    }
#pragma unroll
    for (int d = 8; d >= 1; d >>= 1) {
        float ov1 = __shfl_down_sync(0xffffffffu, v1, d);
        int   oi1 = __shfl_down_sync(0xffffffffu, i1, d);
        float ov2 = __shfl_down_sync(0xffffffffu, v2, d);
        int   oi2 = __shfl_down_sync(0xffffffffu, i2, d);
        if (ov1 > v1 || (ov1 == v1 && oi1 < i1)) { v2 = v1; i2 = i1; v1 = ov1; i1 = oi1; }
        else if (ov1 > v2 || (ov1 == v2 && oi1 < i2)) { v2 = ov1; i2 = oi1; }
        if (ov2 > v1 || (ov2 == v1 && oi2 < i1)) { v2 = v1; i2 = i1; v1 = ov2; i1 = oi2; }
        else if (ov2 > v2 || (ov2 == v2 && oi2 < i2)) { v2 = ov2; i2 = oi2; }
    }
    if (lane == 0)
        g_stage.off[gate] = make_uint4((unsigned)(i1 * EST * 4),
                                       (unsigned)(16 * ((i1 >> 2) & 15)),
                                       (unsigned)(i2 * EST * 4),
                                       (unsigned)(16 * ((i2 >> 2) & 15)));
    if (tid < NGATES * NOUT) {
        int i = tid >> 3, j = tid & 7;
        g_stage.w[i][j] = ow[i * NOUT + j] * sc[j];
    }
}

// ---------------------------------------------------------------------------
// Main: one thread = TWO samples (float2 buffer lanes). Smem op count per
// sample is the binding resource (~4 cyc dispatch per warp-level smem op/SM):
//   gate loop: 2 LDS.64 + 1 STS.64 per gate per warp (64 samples/warp)
//   X load:    4x LDG.128 (coalesced, 4 rows x same 16B chunk) -> register
//              quad transpose -> 4x STS.128 per round; 32 LDG + 32 STS/warp.
// ---------------------------------------------------------------------------
__global__ void __launch_bounds__(BLKT, 3)
circuit_kernel(const float* __restrict__ X, float* __restrict__ out) {
    extern __shared__ float sbuf[];
    const int tid = threadIdx.x;
    const long long base = (long long)blockIdx.x * SPB;

    // --- X transpose: feature-major, swizzled columns, STS.128 quads ---
    {
        const int lane = tid & 31, w = tid >> 5;
        const int c  = lane & 15;        // 16B chunk index (features 4c..4c+3)
        const int sq = lane >> 4;        // sub-quad select
        const float4* Xb = (const float4*)(X + base * NFEAT);
#pragma unroll
        for (int r = 0; r < 8; ++r) {
            int sl = 64 * w + 4 * (2 * r + sq);      // local sample quad base
            const float4* rp = Xb + sl * 16 + c;     // row stride = 16 float4
            float4 v0 = __ldcs(rp + 0 * 16);
            float4 v1 = __ldcs(rp + 1 * 16);
            float4 v2 = __ldcs(rp + 2 * 16);
            float4 v3 = __ldcs(rp + 3 * 16);
            int col = sl ^ (4 * c);                  // swizzled column (quad-aligned)
            float* p = sbuf + (4 * c) * EST + col;
            *(float4*)(p + 0 * EST) = make_float4(v0.x, v1.x, v2.x, v3.x);
            *(float4*)(p + 1 * EST) = make_float4(v0.y, v1.y, v2.y, v3.y);
            *(float4*)(p + 2 * EST) = make_float4(v0.z, v1.z, v2.z, v3.z);
            *(float4*)(p + 3 * EST) = make_float4(v0.w, v1.w, v2.w, v3.w);
        }
    }
    // Const entries (swz((64..65)>>2 & 15) == 0 -> plain columns).
    *(float2*)(sbuf + 64 * EST + 2 * tid) = make_float2(0.0f, 0.0f);
    *(float2*)(sbuf + 65 * EST + 2 * tid) = make_float2(1.0f, 1.0f);
    __syncthreads();

    const char* sb = (const char*)sbuf;
    const unsigned m8 = 8u * tid;        // this thread's pair column (bytes)
    float2 acc[NOUT];
#pragma unroll
    for (int j = 0; j < NOUT; ++j) acc[j] = make_float2(0.0f, 0.0f);

    uint4 o0 = c_p.off[0];
    float2 a = *(const float2*)(sb + o0.x + (m8 ^ o0.y));
    float2 b = *(const float2*)(sb + o0.z + (m8 ^ o0.w));

#pragma unroll
    for (int i = 0; i < NGATES; ++i) {
        float2 g;
        g.x = fmaf(-a.x, b.x, 1.0f);
        g.y = fmaf(-a.y, b.y, 1.0f);

        // STS.64 to slot 66+i (compile-time swizzle constant)
        const unsigned swS = 16u * (((BASEN + i) >> 2) & 15);
        *(float2*)((char*)sb + (unsigned)((BASEN + i) * EST * 4) + (m8 ^ swS)) = g;

        if (i + 1 < NGATES) {            // post-STS prefetch: never stale
            uint4 o = c_p.off[i + 1];
            a = *(const float2*)(sb + o.x + (m8 ^ o.y));
            b = *(const float2*)(sb + o.z + (m8 ^ o.w));
        }

        float4 w0 = *(const float4*)&c_p.w[i][0];    // 2x LDC.128
        float4 w1 = *(const float4*)&c_p.w[i][4];
        acc[0].x = fmaf(g.x, w0.x, acc[0].x);  acc[0].y = fmaf(g.y, w0.x, acc[0].y);
        acc[1].x = fmaf(g.x, w0.y, acc[1].x);  acc[1].y = fmaf(g.y, w0.y, acc[1].y);
        acc[2].x = fmaf(g.x, w0.z, acc[2].x);  acc[2].y = fmaf(g.y, w0.z, acc[2].y);
        acc[3].x = fmaf(g.x, w0.w, acc[3].x);  acc[3].y = fmaf(g.y, w0.w, acc[3].y);
        acc[4].x = fmaf(g.x, w1.x, acc[4].x);  acc[4].y = fmaf(g.y, w1.x, acc[4].y);
        acc[5].x = fmaf(g.x, w1.y, acc[5].x);  acc[5].y = fmaf(g.y, w1.y, acc[5].y);
        acc[6].x = fmaf(g.x, w1.z, acc[6].x);  acc[6].y = fmaf(g.y, w1.z, acc[6].y);
        acc[7].x = fmaf(g.x, w1.w, acc[7].x);  acc[7].y = fmaf(g.y, w1.w, acc[7].y);
    }

    // Output: two samples' 8 floats each = 64B contiguous per thread.
    float4* op = (float4*)(out + (base + 2 * tid) * NOUT);
    __stcs(&op[0], make_float4(acc[0].x, acc[1].x, acc[2].x, acc[3].x));
    __stcs(&op[1], make_float4(acc[4].x, acc[5].x, acc[6].x, acc[7].x));
    __stcs(&op[2], make_float4(acc[0].y, acc[1].y, acc[2].y, acc[3].y));
    __stcs(&op[3], make_float4(acc[4].y, acc[5].y, acc[6].y, acc[7].y));
}

// ---------------------------------------------------------------------------
// Launch: prep -> ONE memcpy into the constant bank -> main kernel (3 nodes).
// ---------------------------------------------------------------------------
extern "C" void kernel_launch(void* const* d_in, const int* in_sizes, int n_in,
                              void* d_out, int out_size) {
    const float* X  = (const float*)d_in[0];  // (524288, 64)
    const float* gw = (const float*)d_in[1];  // (64, 130)
    const float* ow = (const float*)d_in[2];  // (64, 8)
    const float* sc = (const float*)d_in[3];  // (8,)
    float* out = (float*)d_out;               // (524288, 8)

    cudaFuncSetAttribute((const void*)circuit_kernel,
                         cudaFuncAttributeMaxDynamicSharedMemorySize, SMEM_BYTES);

    prep_kernel<<<1, 1024>>>(gw, ow, sc);

    void* gp = nullptr;
    cudaGetSymbolAddress(&gp, g_stage);
    cudaMemcpyToSymbolAsync(c_p, gp, sizeof(Params), 0,
                            cudaMemcpyDeviceToDevice, 0);

    circuit_kernel<<<NSAMPLES / SPB, BLKT, SMEM_BYTES>>>(X, out);
}